// round 1
// baseline (speedup 1.0000x reference)
#include <cuda_runtime.h>
#include <stdint.h>

// RoPE: x (B,H,S,128) fp32, token_positions (S,) int32,
// cos_table/sin_table (8192, 64) fp32.
// out[..., 2k]   = c*x1 - s*x2
// out[..., 2k+1] = s*x1 + c*x2
//
// One thread per float4 (two interleaved pairs). 32 float4 per head row.

__global__ void __launch_bounds__(256)
rope_f4_kernel(const float4* __restrict__ x,
               const int*    __restrict__ tok_pos,
               const float2* __restrict__ cos_t,   // row stride 32 float2
               const float2* __restrict__ sin_t,
               float4*       __restrict__ out,
               int n4, int seq)
{
    int i = blockIdx.x * blockDim.x + threadIdx.x;
    if (i >= n4) return;

    int row = i >> 5;        // 128 floats = 32 float4 per row
    int q   = i & 31;        // float4 index within row -> pairs (2q, 2q+1)
    int pos = row % seq;     // seq is the dim just above d_k
    int p   = __ldg(&tok_pos[pos]);

    // table row = p, 64 floats = 32 float2; pair k=2q -> float2 index q
    float2 c = __ldg(&cos_t[p * 32 + q]);
    float2 s = __ldg(&sin_t[p * 32 + q]);

    float4 v = x[i];
    float4 o;
    o.x = fmaf(c.x, v.x, -s.x * v.y);
    o.y = fmaf(s.x, v.x,  c.x * v.y);
    o.z = fmaf(c.y, v.z, -s.y * v.w);
    o.w = fmaf(s.y, v.z,  c.y * v.w);
    out[i] = o;
}

extern "C" void kernel_launch(void* const* d_in, const int* in_sizes, int n_in,
                              void* d_out, int out_size)
{
    const float4* x     = (const float4*)d_in[0];
    const int*    tpos  = (const int*)   d_in[1];
    const float2* cos_t = (const float2*)d_in[2];
    const float2* sin_t = (const float2*)d_in[3];
    float4*       out   = (float4*)      d_out;

    int seq = in_sizes[1];          // token_positions element count = SEQ
    int n4  = out_size / 4;         // number of float4s

    int threads = 256;
    int blocks  = (n4 + threads - 1) / threads;
    rope_f4_kernel<<<blocks, threads>>>(x, tpos, cos_t, sin_t, out, n4, seq);
}

// round 2
// speedup vs baseline: 1.0598x; 1.0598x over previous
#include <cuda_runtime.h>
#include <stdint.h>

// RoPE: x (B,H,S,128) fp32, token_positions (S,) int32,
// cos_table/sin_table (8192, 64) fp32.
// One thread handles UNROLL float4s (grid-strided, coalesced), loads
// front-batched for MLP.

#define UNROLL 4

template<bool POW2>
__global__ void __launch_bounds__(256)
rope_f4_kernel(const float4* __restrict__ x,
               const int*    __restrict__ tok_pos,
               const float2* __restrict__ cos_t,   // row stride 32 float2
               const float2* __restrict__ sin_t,
               float4*       __restrict__ out,
               int n4, int seq, int seq_mask)
{
    const int stride = gridDim.x * blockDim.x;
    const int base   = blockIdx.x * blockDim.x + threadIdx.x;

    int  idx[UNROLL];
    bool ok [UNROLL];
#pragma unroll
    for (int k = 0; k < UNROLL; k++) {
        idx[k] = base + k * stride;
        ok[k]  = idx[k] < n4;
    }

    // Batch 1: x loads (independent LDG.128) + token-position loads
    float4 v[UNROLL];
    int    p[UNROLL];
#pragma unroll
    for (int k = 0; k < UNROLL; k++)
        if (ok[k]) v[k] = x[idx[k]];
#pragma unroll
    for (int k = 0; k < UNROLL; k++) {
        if (ok[k]) {
            int row = idx[k] >> 5;                 // 32 float4 per 128-elem row
            int pos = POW2 ? (row & seq_mask) : (row % seq);
            p[k] = __ldg(&tok_pos[pos]);
        }
    }

    // Batch 2: table gathers (L2-resident after first wave)
    float2 c[UNROLL], s[UNROLL];
#pragma unroll
    for (int k = 0; k < UNROLL; k++) {
        if (ok[k]) {
            int q = idx[k] & 31;
            c[k] = __ldg(&cos_t[p[k] * 32 + q]);
            s[k] = __ldg(&sin_t[p[k] * 32 + q]);
        }
    }

    // Compute + store
#pragma unroll
    for (int k = 0; k < UNROLL; k++) {
        if (ok[k]) {
            float4 o;
            o.x = fmaf(c[k].x, v[k].x, -s[k].x * v[k].y);
            o.y = fmaf(s[k].x, v[k].x,  c[k].x * v[k].y);
            o.z = fmaf(c[k].y, v[k].z, -s[k].y * v[k].w);
            o.w = fmaf(s[k].y, v[k].z,  c[k].y * v[k].w);
            out[idx[k]] = o;
        }
    }
}

extern "C" void kernel_launch(void* const* d_in, const int* in_sizes, int n_in,
                              void* d_out, int out_size)
{
    const float4* x     = (const float4*)d_in[0];
    const int*    tpos  = (const int*)   d_in[1];
    const float2* cos_t = (const float2*)d_in[2];
    const float2* sin_t = (const float2*)d_in[3];
    float4*       out   = (float4*)      d_out;

    int seq = in_sizes[1];          // token_positions element count = SEQ
    int n4  = out_size / 4;         // number of float4s

    const int threads = 256;
    int blocks = (n4 + threads * UNROLL - 1) / (threads * UNROLL);

    bool pow2 = (seq & (seq - 1)) == 0;
    if (pow2)
        rope_f4_kernel<true ><<<blocks, threads>>>(x, tpos, cos_t, sin_t, out,
                                                   n4, seq, seq - 1);
    else
        rope_f4_kernel<false><<<blocks, threads>>>(x, tpos, cos_t, sin_t, out,
                                                   n4, seq, 0);
}

// round 3
// speedup vs baseline: 1.0613x; 1.0014x over previous
#include <cuda_runtime.h>
#include <stdint.h>

// RoPE: x (B,H,S,128) fp32, token_positions (S,) int32,
// cos_table/sin_table (8192, 64) fp32.
//
// Bulk kernel: CTA owns 2048 contiguous float4s; each thread handles 8 at
// compile-time offsets k*256 (immediate LDG offsets, no per-item IMAD).
// Streaming cache hints on x/out; tables stay in L2.

#define THREADS 256
#define UN 8
#define CHUNK (THREADS * UN)

template<bool POW2>
__global__ void __launch_bounds__(THREADS)
rope_bulk(const float4* __restrict__ x,
          const int*    __restrict__ tok_pos,
          const float2* __restrict__ cos_t,   // row stride 32 float2
          const float2* __restrict__ sin_t,
          float4*       __restrict__ out,
          int seq, int seq_mask)
{
    const int base = blockIdx.x * CHUNK + threadIdx.x;
    const int q    = threadIdx.x & 31;       // float4 col within 128-elem row
    const int row0 = base >> 5;

    // Batch 1: 8 independent 16B loads (DRAM stream), evict-first
    float4 v[UN];
#pragma unroll
    for (int k = 0; k < UN; k++)
        v[k] = __ldcs(&x[base + k * THREADS]);

    // Batch 2: token positions (tiny, L2/L1 resident)
    int p[UN];
#pragma unroll
    for (int k = 0; k < UN; k++) {
        int row = row0 + k * (THREADS / 32);
        int pos = POW2 ? (row & seq_mask) : (row % seq);
        p[k] = __ldg(&tok_pos[pos]);
    }

    // Batch 3: table gathers (L2-resident, warp-coalesced 256B)
    float2 c[UN], s[UN];
#pragma unroll
    for (int k = 0; k < UN; k++) {
        c[k] = __ldg(&cos_t[p[k] * 32 + q]);
        s[k] = __ldg(&sin_t[p[k] * 32 + q]);
    }

    // Compute + streaming stores
#pragma unroll
    for (int k = 0; k < UN; k++) {
        float4 o;
        o.x = fmaf(c[k].x, v[k].x, -s[k].x * v[k].y);
        o.y = fmaf(s[k].x, v[k].x,  c[k].x * v[k].y);
        o.z = fmaf(c[k].y, v[k].z, -s[k].y * v[k].w);
        o.w = fmaf(s[k].y, v[k].z,  c[k].y * v[k].w);
        __stcs(&out[base + k * THREADS], o);
    }
}

// Checked tail for n4 not divisible by CHUNK.
template<bool POW2>
__global__ void __launch_bounds__(THREADS)
rope_tail(const float4* __restrict__ x,
          const int*    __restrict__ tok_pos,
          const float2* __restrict__ cos_t,
          const float2* __restrict__ sin_t,
          float4*       __restrict__ out,
          int start, int n4, int seq, int seq_mask)
{
    int i = start + blockIdx.x * blockDim.x + threadIdx.x;
    if (i >= n4) return;
    int row = i >> 5;
    int q   = i & 31;
    int pos = POW2 ? (row & seq_mask) : (row % seq);
    int p   = __ldg(&tok_pos[pos]);
    float2 c = __ldg(&cos_t[p * 32 + q]);
    float2 s = __ldg(&sin_t[p * 32 + q]);
    float4 v = x[i];
    float4 o;
    o.x = fmaf(c.x, v.x, -s.x * v.y);
    o.y = fmaf(s.x, v.x,  c.x * v.y);
    o.z = fmaf(c.y, v.z, -s.y * v.w);
    o.w = fmaf(s.y, v.z,  c.y * v.w);
    out[i] = o;
}

extern "C" void kernel_launch(void* const* d_in, const int* in_sizes, int n_in,
                              void* d_out, int out_size)
{
    const float4* x     = (const float4*)d_in[0];
    const int*    tpos  = (const int*)   d_in[1];
    const float2* cos_t = (const float2*)d_in[2];
    const float2* sin_t = (const float2*)d_in[3];
    float4*       out   = (float4*)      d_out;

    int seq = in_sizes[1];
    int n4  = out_size / 4;

    int  blocks = n4 / CHUNK;
    int  n_bulk = blocks * CHUNK;
    int  tail   = n4 - n_bulk;
    bool pow2   = (seq & (seq - 1)) == 0;

    if (blocks > 0) {
        if (pow2)
            rope_bulk<true ><<<blocks, THREADS>>>(x, tpos, cos_t, sin_t, out,
                                                  seq, seq - 1);
        else
            rope_bulk<false><<<blocks, THREADS>>>(x, tpos, cos_t, sin_t, out,
                                                  seq, 0);
    }
    if (tail > 0) {
        int tblocks = (tail + THREADS - 1) / THREADS;
        if (pow2)
            rope_tail<true ><<<tblocks, THREADS>>>(x, tpos, cos_t, sin_t, out,
                                                   n_bulk, n4, seq, seq - 1);
        else
            rope_tail<false><<<tblocks, THREADS>>>(x, tpos, cos_t, sin_t, out,
                                                   n_bulk, n4, seq, 0);
    }
}

// round 4
// speedup vs baseline: 1.0806x; 1.0182x over previous
#include <cuda_runtime.h>
#include <stdint.h>

// RoPE: x (B,H,S,128) fp32, token_positions (S,) int32,
// cos_table/sin_table (8192, 64) fp32.
//
// Bulk: CTA owns 1024 contiguous float4s; each thread handles 4 at
// compile-time offsets k*256 (immediate LDG offsets). UN=4 keeps the
// per-thread MLP below the L1tex-queue contention knee; launch_bounds
// caps regs to lift occupancy.

#define THREADS 256
#define UN 4
#define CHUNK (THREADS * UN)

template<bool POW2>
__global__ void __launch_bounds__(THREADS, 6)
rope_bulk(const float4* __restrict__ x,
          const int*    __restrict__ tok_pos,
          const float2* __restrict__ cos_t,   // row stride 32 float2
          const float2* __restrict__ sin_t,
          float4*       __restrict__ out,
          int seq, int seq_mask)
{
    const int base = blockIdx.x * CHUNK + threadIdx.x;
    const int q    = threadIdx.x & 31;        // float4 col within 128-elem row
    const int row0 = base >> 5;

    // Batch 1: 4 independent 16B DRAM loads
    float4 v[UN];
#pragma unroll
    for (int k = 0; k < UN; k++)
        v[k] = x[base + k * THREADS];

    // Batch 2: token positions (tiny, cache resident)
    int p[UN];
#pragma unroll
    for (int k = 0; k < UN; k++) {
        int row = row0 + k * (THREADS / 32);
        int pos = POW2 ? (row & seq_mask) : (row % seq);
        p[k] = __ldg(&tok_pos[pos]);
    }

    // Batch 3: table gathers (L2-resident, warp-coalesced 256B)
    float2 c[UN], s[UN];
#pragma unroll
    for (int k = 0; k < UN; k++) {
        c[k] = __ldg(&cos_t[p[k] * 32 + q]);
        s[k] = __ldg(&sin_t[p[k] * 32 + q]);
    }

    // Compute + stores
#pragma unroll
    for (int k = 0; k < UN; k++) {
        float4 o;
        o.x = fmaf(c[k].x, v[k].x, -s[k].x * v[k].y);
        o.y = fmaf(s[k].x, v[k].x,  c[k].x * v[k].y);
        o.z = fmaf(c[k].y, v[k].z, -s[k].y * v[k].w);
        o.w = fmaf(s[k].y, v[k].z,  c[k].y * v[k].w);
        out[base + k * THREADS] = o;
    }
}

// Checked tail for n4 not divisible by CHUNK.
template<bool POW2>
__global__ void __launch_bounds__(THREADS)
rope_tail(const float4* __restrict__ x,
          const int*    __restrict__ tok_pos,
          const float2* __restrict__ cos_t,
          const float2* __restrict__ sin_t,
          float4*       __restrict__ out,
          int start, int n4, int seq, int seq_mask)
{
    int i = start + blockIdx.x * blockDim.x + threadIdx.x;
    if (i >= n4) return;
    int row = i >> 5;
    int q   = i & 31;
    int pos = POW2 ? (row & seq_mask) : (row % seq);
    int p   = __ldg(&tok_pos[pos]);
    float2 c = __ldg(&cos_t[p * 32 + q]);
    float2 s = __ldg(&sin_t[p * 32 + q]);
    float4 v = x[i];
    float4 o;
    o.x = fmaf(c.x, v.x, -s.x * v.y);
    o.y = fmaf(s.x, v.x,  c.x * v.y);
    o.z = fmaf(c.y, v.z, -s.y * v.w);
    o.w = fmaf(s.y, v.z,  c.y * v.w);
    out[i] = o;
}

extern "C" void kernel_launch(void* const* d_in, const int* in_sizes, int n_in,
                              void* d_out, int out_size)
{
    const float4* x     = (const float4*)d_in[0];
    const int*    tpos  = (const int*)   d_in[1];
    const float2* cos_t = (const float2*)d_in[2];
    const float2* sin_t = (const float2*)d_in[3];
    float4*       out   = (float4*)      d_out;

    int seq = in_sizes[1];
    int n4  = out_size / 4;

    int  blocks = n4 / CHUNK;
    int  n_bulk = blocks * CHUNK;
    int  tail   = n4 - n_bulk;
    bool pow2   = (seq & (seq - 1)) == 0;

    if (blocks > 0) {
        if (pow2)
            rope_bulk<true ><<<blocks, THREADS>>>(x, tpos, cos_t, sin_t, out,
                                                  seq, seq - 1);
        else
            rope_bulk<false><<<blocks, THREADS>>>(x, tpos, cos_t, sin_t, out,
                                                  seq, 0);
    }
    if (tail > 0) {
        int tblocks = (tail + THREADS - 1) / THREADS;
        if (pow2)
            rope_tail<true ><<<tblocks, THREADS>>>(x, tpos, cos_t, sin_t, out,
                                                   n_bulk, n4, seq, seq - 1);
        else
            rope_tail<false><<<tblocks, THREADS>>>(x, tpos, cos_t, sin_t, out,
                                                   n_bulk, n4, seq, 0);
    }
}